// round 2
// baseline (speedup 1.0000x reference)
#include <cuda_runtime.h>
#include <cstdint>

#define NN      50000
#define NMSG    200
#define WSTR    36          // padded float stride for shared weight rows (bank-stagger)

// ---------------------------------------------------------------------------
// Static device scratch
// ---------------------------------------------------------------------------
__device__ __align__(16) float g_x0[NN * 30];
__device__ __align__(16) float g_x1[NN * 30];
__device__ __align__(16) float g_A [NN * NMSG];
__device__ __align__(16) float g_B [NN * NMSG];
__device__ int g_is64;

// ---------------------------------------------------------------------------
// Packed f32x2 helpers (Blackwell FFMA2 / FADD2)
// ---------------------------------------------------------------------------
typedef unsigned long long u64;

__device__ __forceinline__ u64 fma2(u64 a, u64 b, u64 c) {
    u64 d;
    asm("fma.rn.f32x2 %0, %1, %2, %3;" : "=l"(d) : "l"(a), "l"(b), "l"(c));
    return d;
}
__device__ __forceinline__ u64 add2(u64 a, u64 b) {
    u64 d;
    asm("add.rn.f32x2 %0, %1, %2;" : "=l"(d) : "l"(a), "l"(b));
    return d;
}
__device__ __forceinline__ u64 pack2(float x) {
    u64 d;
    asm("mov.b64 %0, {%1, %1};" : "=l"(d) : "f"(x));
    return d;
}
__device__ __forceinline__ float2 unpack2(u64 a) {
    float2 f;
    asm("mov.b64 {%0, %1}, %2;" : "=f"(f.x), "=f"(f.y) : "l"(a));
    return f;
}

// ---------------------------------------------------------------------------
// Edge dtype detection (int64 per reference vs int32 if JAX x64 disabled)
// ---------------------------------------------------------------------------
__global__ void detect_edges_kernel(const long long* __restrict__ e64) {
    if (threadIdx.x == 0 && blockIdx.x == 0) {
        int ok = 1;
        for (int i = 0; i < 16; i++) {
            long long v = e64[i];
            if (v < 0 || v >= NN) ok = 0;
        }
        g_is64 = ok;
    }
}

// ---------------------------------------------------------------------------
// Per-node precompute: A[n,k] = relu?(x[n])·Wm1[0:C,k] + bm1[k]
//                      B[n,k] = relu?(x[n])·Wm1[C:2C,k]
// ---------------------------------------------------------------------------
template <int C_IN, bool RELU_IN>
__global__ void precomp_ab_kernel(const float* __restrict__ x,
                                  const float* __restrict__ Wm1,
                                  const float* __restrict__ bm1,
                                  float* __restrict__ A,
                                  float* __restrict__ B,
                                  int N) {
    int idx = blockIdx.x * blockDim.x + threadIdx.x;
    if (idx >= N * NMSG) return;
    int n = idx / NMSG;
    int k = idx - n * NMSG;
    float a = bm1[k];
    float b = 0.f;
#pragma unroll
    for (int c = 0; c < C_IN; c++) {
        float xv = x[(size_t)n * C_IN + c];
        if (RELU_IN) xv = fmaxf(xv, 0.f);
        a = fmaf(xv, Wm1[c * NMSG + k], a);
        b = fmaf(xv, Wm1[(C_IN + c) * NMSG + k], b);
    }
    A[idx] = a;
    B[idx] = b;
}

// ---------------------------------------------------------------------------
// Node self-term + aggregation buffer init
// ---------------------------------------------------------------------------
template <int C_IN, int C_OUT, bool RELU_IN>
__global__ void node_init_kernel(const float* __restrict__ x,
                                 const float* __restrict__ W1,
                                 const float* __restrict__ b1,
                                 float* __restrict__ out,
                                 int N) {
    int idx = blockIdx.x * blockDim.x + threadIdx.x;
    if (idx >= N * C_OUT) return;
    int n  = idx / C_OUT;
    int co = idx - n * C_OUT;
    float v = b1[co];
#pragma unroll
    for (int c = 0; c < C_IN; c++) {
        float xv = x[(size_t)n * C_IN + c];
        if (RELU_IN) xv = fmaxf(xv, 0.f);
        v = fmaf(xv, W1[c * C_OUT + co], v);
    }
    out[idx] = v;
}

// ---------------------------------------------------------------------------
// Edge kernel: 8 lanes cooperate per edge (octet). 4 edges per warp,
// 32 edges per 256-thread block iteration; grid-stride over edge tiles.
//
//   h_k  = relu( A[dst,k] + B[src,k] + w0*WE0_k + w1*WE1_k )   (k split by lane)
//   m    = h @ Wm2                (per-lane partial, packed f32x2, octet-reduced)
//   t_c  = (m_c + bm2_c) * (xi_c - xj_c)
//   msg  = t @ W2 + b2            (per-lane partial over owned c, octet-reduced)
//   atomicAdd into out[dst]
// ---------------------------------------------------------------------------
template <int C_IN, int C_OUT, bool RELU_IN>
__global__ void __launch_bounds__(256, 2)
edge_kernel(const void* __restrict__ edges,
            const float* __restrict__ ea,
            const float* __restrict__ x,
            const float* __restrict__ A,
            const float* __restrict__ B,
            const float* __restrict__ Wm1,
            const float* __restrict__ Wm2,
            const float* __restrict__ bm2,
            const float* __restrict__ W2,
            const float* __restrict__ b2,
            float* __restrict__ out,
            int E) {
    constexpr int NP4  = (C_IN + 3) / 4;       // float4 groups for Wm2 row / m
    constexpr int NPR  = NP4 * 2;              // f32x2 pairs for m accumulator
    constexpr int OP4  = (C_OUT + 3) / 4;
    constexpr int OPR  = OP4 * 2;

    __shared__ __align__(16) float sWE[2 * NMSG];        // edge-attr rows of Wm1
    __shared__ __align__(16) float sWm2[NMSG * WSTR];    // [k][c], padded, zero-filled
    __shared__ __align__(16) float sW2[C_IN * WSTR];     // [c][co], padded, zero-filled
    __shared__ float sbm2[C_IN];
    __shared__ float sb2[32];

    const int tid = threadIdx.x;
    for (int i = tid; i < 2 * NMSG; i += 256) sWE[i] = Wm1[2 * C_IN * NMSG + i];
    for (int i = tid; i < NMSG * WSTR; i += 256) {
        int k = i / WSTR, c = i - k * WSTR;
        sWm2[i] = (c < C_IN) ? Wm2[k * C_IN + c] : 0.f;
    }
    for (int i = tid; i < C_IN * WSTR; i += 256) {
        int c = i / WSTR, co = i - c * WSTR;
        sW2[i] = (co < C_OUT) ? W2[c * C_OUT + co] : 0.f;
    }
    for (int i = tid; i < C_IN; i += 256) sbm2[i] = bm2[i];
    for (int i = tid; i < 32; i += 256) sb2[i] = (i < C_OUT) ? b2[i] : 0.f;
    __syncthreads();

    const int lane  = tid & 31;
    const int warp  = tid >> 5;
    const int o     = lane & 7;          // lane within octet
    const int eLoc  = lane >> 3;         // edge within warp (0..3)
    const int slot  = warp * 4 + eLoc;   // edge within 32-edge tile
    const bool is64 = (g_is64 != 0);

    const int nTiles = (E + 31) / 32;

    for (int tile = blockIdx.x; tile < nTiles; tile += gridDim.x) {
        const int e = tile * 32 + slot;
        const bool valid = (e < E);

        int src = 0, dst = 0;
        float2 w = make_float2(0.f, 0.f);
        if (valid) {
            if (is64) {
                const long long* p = (const long long*)edges;
                src = (int)p[e];
                dst = (int)p[(size_t)E + e];
            } else {
                const int* p = (const int*)edges;
                src = p[e];
                dst = p[E + e];
            }
            w = ((const float2*)ea)[e];
        }

        // xdiff for owned channels c = o + 8*j
        float xd[4];
#pragma unroll
        for (int j = 0; j < 4; j++) {
            int c = o + 8 * j;
            float d = 0.f;
            if (c < C_IN) {
                float xi = x[(size_t)dst * C_IN + c];
                float xj = x[(size_t)src * C_IN + c];
                if (RELU_IN) { xi = fmaxf(xi, 0.f); xj = fmaxf(xj, 0.f); }
                d = xi - xj;
            }
            xd[j] = d;
        }

        const float4* A4 = (const float4*)(A + (size_t)dst * NMSG);
        const float4* B4 = (const float4*)(B + (size_t)src * NMSG);
        const float4* W0 = (const float4*)(sWE);
        const float4* W1r = (const float4*)(sWE + NMSG);

        u64 acc[NPR];
#pragma unroll
        for (int p = 0; p < NPR; p++) acc[p] = 0ull;

        // k-groups owned by this lane: g4 = 8*i + o (i<6), plus 48+o for o<2
#pragma unroll
        for (int i = 0; i < 7; i++) {
            int g4;
            if (i < 6)       g4 = i * 8 + o;
            else if (o < 2)  g4 = 48 + o;
            else             break;

            float4 a = A4[g4];
            float4 b = B4[g4];
            float4 u0 = W0[g4];
            float4 u1 = W1r[g4];
            float h[4];
            h[0] = fmaxf(fmaf(w.x, u0.x, fmaf(w.y, u1.x, a.x + b.x)), 0.f);
            h[1] = fmaxf(fmaf(w.x, u0.y, fmaf(w.y, u1.y, a.y + b.y)), 0.f);
            h[2] = fmaxf(fmaf(w.x, u0.z, fmaf(w.y, u1.z, a.z + b.z)), 0.f);
            h[3] = fmaxf(fmaf(w.x, u0.w, fmaf(w.y, u1.w, a.w + b.w)), 0.f);

            int k0 = g4 * 4;
#pragma unroll
            for (int t = 0; t < 4; t++) {
                u64 h2 = pack2(h[t]);
                const u64* row = (const u64*)(sWm2 + (k0 + t) * WSTR);
#pragma unroll
                for (int p = 0; p < NPR; p++)
                    acc[p] = fma2(h2, row[p], acc[p]);
            }
        }

        // Reduce m across the octet (butterfly -> all lanes hold full m)
#pragma unroll
        for (int off = 4; off > 0; off >>= 1) {
#pragma unroll
            for (int p = 0; p < NPR; p++)
                acc[p] = add2(acc[p], __shfl_xor_sync(0xffffffffu, acc[p], off));
        }

        // t_c for owned c, then partial msg = t @ W2
        u64 macc[OPR];
#pragma unroll
        for (int p = 0; p < OPR; p++) macc[p] = 0ull;

#pragma unroll
        for (int j = 0; j < 4; j++) {
            int c = o + 8 * j;
            if (c < C_IN) {
                float2 mp = unpack2(acc[c >> 1]);
                float m = (c & 1) ? mp.y : mp.x;
                float t = (m + sbm2[c]) * xd[j];
                u64 t2 = pack2(t);
                const u64* row = (const u64*)(sW2 + c * WSTR);
#pragma unroll
                for (int p = 0; p < OPR; p++)
                    macc[p] = fma2(t2, row[p], macc[p]);
            }
        }

        // Reduce msg across octet
#pragma unroll
        for (int off = 4; off > 0; off >>= 1) {
#pragma unroll
            for (int p = 0; p < OPR; p++)
                macc[p] = add2(macc[p], __shfl_xor_sync(0xffffffffu, macc[p], off));
        }

        // Owned output channels -> atomics
        if (valid) {
            float* op = out + (size_t)dst * C_OUT;
#pragma unroll
            for (int j = 0; j < 4; j++) {
                int co = o + 8 * j;
                if (co < C_OUT) {
                    float2 vp = unpack2(macc[co >> 1]);
                    float v = ((co & 1) ? vp.y : vp.x) + sb2[co];
                    atomicAdd(op + co, v);
                }
            }
        }
    }
}

// ---------------------------------------------------------------------------
// Host-side layer driver
// ---------------------------------------------------------------------------
template <int C_IN, int C_OUT, bool RELU_IN>
static void run_layer(const float* xin,
                      const float* const* W,   // W1,b1,Wm1,bm1,Wm2,bm2,W2,b2
                      const void* edges, const float* ew,
                      float* Abuf, float* Bbuf,
                      float* xout,
                      int N, int E) {
    precomp_ab_kernel<C_IN, RELU_IN><<<(N * NMSG + 255) / 256, 256>>>(
        xin, W[2], W[3], Abuf, Bbuf, N);
    node_init_kernel<C_IN, C_OUT, RELU_IN><<<(N * C_OUT + 255) / 256, 256>>>(
        xin, W[0], W[1], xout, N);
    edge_kernel<C_IN, C_OUT, RELU_IN><<<592, 256>>>(
        edges, ew, xin, Abuf, Bbuf, W[2], W[4], W[5], W[6], W[7], xout, E);
}

extern "C" void kernel_launch(void* const* d_in, const int* in_sizes, int n_in,
                              void* d_out, int out_size) {
    const float* feat  = (const float*)d_in[0];
    const void*  edges = d_in[1];
    const float* ew    = (const float*)d_in[2];

    const float* P[24];
    for (int i = 0; i < 24; i++) P[i] = (const float*)d_in[3 + i];
    // P[0..7] = layer d, P[8..15] = layer h, P[16..23] = layer o

    int N = in_sizes[0];        // NUM_IN == 1 -> element count == node count
    int E = in_sizes[2] / 2;    // weights is [E,2]

    float *x0, *x1, *A, *B;
    cudaGetSymbolAddress((void**)&x0, g_x0);
    cudaGetSymbolAddress((void**)&x1, g_x1);
    cudaGetSymbolAddress((void**)&A,  g_A);
    cudaGetSymbolAddress((void**)&B,  g_B);

    detect_edges_kernel<<<1, 32>>>((const long long*)edges);

    // d layer: input = features (no input relu); outputs stored pre-activation,
    // relu applied at read by all consumers of the next layer.
    run_layer<1, 30, false>(feat, P + 0,  edges, ew, A, B, x0, N, E);
    run_layer<30, 30, true>(x0,  P + 8,  edges, ew, A, B, x1, N, E);
    run_layer<30, 30, true>(x1,  P + 8,  edges, ew, A, B, x0, N, E);
    run_layer<30, 30, true>(x0,  P + 8,  edges, ew, A, B, x1, N, E);
    run_layer<30, 1, true>(x1,   P + 16, edges, ew, A, B, (float*)d_out, N, E);
}

// round 3
// speedup vs baseline: 3.4727x; 3.4727x over previous
#include <cuda_runtime.h>
#include <cstdint>

#define NN      50000
#define NE      800000
#define NMSG    200

// ---------------------------------------------------------------------------
// Static device scratch
// ---------------------------------------------------------------------------
__device__ __align__(16) float g_x0[NN * 30];
__device__ __align__(16) float g_x1[NN * 30];
__device__ __align__(16) float g_A [NN * NMSG];
__device__ __align__(16) float g_B [NN * NMSG];
__device__ int g_is64;
__device__ int g_cnt[NN];
__device__ int g_ofs[NN];
__device__ int g_ssrc[NE];
__device__ int g_sdst[NE];
__device__ __align__(8) float2 g_sw[NE];

// ---------------------------------------------------------------------------
// Edge dtype detection (int64 per reference vs int32 if JAX x64 disabled)
// ---------------------------------------------------------------------------
__global__ void detect_edges_kernel(const long long* __restrict__ e64) {
    if (threadIdx.x == 0 && blockIdx.x == 0) {
        int ok = 1;
        for (int i = 0; i < 16; i++) {
            long long v = e64[i];
            if (v < 0 || v >= NN) ok = 0;
        }
        g_is64 = ok;
    }
}

__device__ __forceinline__ int load_idx(const void* edges, long long pos, bool is64) {
    if (is64) return (int)((const long long*)edges)[pos];
    return ((const int*)edges)[pos];
}

// ---------------------------------------------------------------------------
// Counting sort by dst (kernels run every launch; graph-capturable)
// ---------------------------------------------------------------------------
__global__ void zero_hist_kernel(int N) {
    int i = blockIdx.x * blockDim.x + threadIdx.x;
    if (i < N) g_cnt[i] = 0;
}

__global__ void hist_kernel(const void* __restrict__ edges, int E) {
    int e = blockIdx.x * blockDim.x + threadIdx.x;
    if (e >= E) return;
    bool is64 = (g_is64 != 0);
    int dst = load_idx(edges, (long long)E + e, is64);
    atomicAdd(&g_cnt[dst], 1);
}

// single-block exclusive scan over g_cnt -> g_ofs
__global__ void scan_kernel(int N) {
    __shared__ int s[1024];
    __shared__ int carry;
    if (threadIdx.x == 0) carry = 0;
    __syncthreads();
    for (int base = 0; base < N; base += 1024) {
        int i = base + (int)threadIdx.x;
        int v = (i < N) ? g_cnt[i] : 0;
        s[threadIdx.x] = v;
        __syncthreads();
        for (int off = 1; off < 1024; off <<= 1) {
            int t = (threadIdx.x >= off) ? s[threadIdx.x - off] : 0;
            __syncthreads();
            s[threadIdx.x] += t;
            __syncthreads();
        }
        int incl = s[threadIdx.x];
        int tileTotal = s[1023];
        if (i < N) g_ofs[i] = carry + incl - v;
        __syncthreads();
        if (threadIdx.x == 0) carry += tileTotal;
        __syncthreads();
    }
}

__global__ void scatter_kernel(const void* __restrict__ edges,
                               const float* __restrict__ ea, int E) {
    int e = blockIdx.x * blockDim.x + threadIdx.x;
    if (e >= E) return;
    bool is64 = (g_is64 != 0);
    int src = load_idx(edges, e, is64);
    int dst = load_idx(edges, (long long)E + e, is64);
    int p = atomicAdd(&g_ofs[dst], 1);
    g_ssrc[p] = src;
    g_sdst[p] = dst;
    g_sw[p]   = ((const float2*)ea)[e];
}

// ---------------------------------------------------------------------------
// Per-node precompute: A[n,k] = relu?(x[n])·Wm1[0:C,k] + bm1[k]
//                      B[n,k] = relu?(x[n])·Wm1[C:2C,k]
// ---------------------------------------------------------------------------
template <int C_IN, bool RELU_IN>
__global__ void precomp_ab_kernel(const float* __restrict__ x,
                                  const float* __restrict__ Wm1,
                                  const float* __restrict__ bm1,
                                  float* __restrict__ A,
                                  float* __restrict__ B,
                                  int N) {
    int idx = blockIdx.x * blockDim.x + threadIdx.x;
    if (idx >= N * NMSG) return;
    int n = idx / NMSG;
    int k = idx - n * NMSG;
    float a = bm1[k];
    float b = 0.f;
#pragma unroll
    for (int c = 0; c < C_IN; c++) {
        float xv = x[(size_t)n * C_IN + c];
        if (RELU_IN) xv = fmaxf(xv, 0.f);
        a = fmaf(xv, Wm1[c * NMSG + k], a);
        b = fmaf(xv, Wm1[(C_IN + c) * NMSG + k], b);
    }
    A[idx] = a;
    B[idx] = b;
}

// ---------------------------------------------------------------------------
// Node self-term + aggregation buffer init
// ---------------------------------------------------------------------------
template <int C_IN, int C_OUT, bool RELU_IN>
__global__ void node_init_kernel(const float* __restrict__ x,
                                 const float* __restrict__ W1,
                                 const float* __restrict__ b1,
                                 float* __restrict__ out,
                                 int N) {
    int idx = blockIdx.x * blockDim.x + threadIdx.x;
    if (idx >= N * C_OUT) return;
    int n  = idx / C_OUT;
    int co = idx - n * C_OUT;
    float v = b1[co];
#pragma unroll
    for (int c = 0; c < C_IN; c++) {
        float xv = x[(size_t)n * C_IN + c];
        if (RELU_IN) xv = fmaxf(xv, 0.f);
        v = fmaf(xv, W1[c * C_OUT + co], v);
    }
    out[idx] = v;
}

// ---------------------------------------------------------------------------
// Edge kernel (thread-per-edge, dst-sorted inputs).
//   h_k  = relu( A[dst,k] + B[src,k] + w0*WE0_k + w1*WE1_k )
//   m_c  = sum_k h_k * Wm2[k,c]
//   t_c  = (m_c + bm2_c) * (xi_c - xj_c)
//   msg  = t @ W2 + b2   -> atomicAdd into out[dst]
// ---------------------------------------------------------------------------
template <int C_IN, int C_OUT, bool RELU_IN>
__global__ void __launch_bounds__(256)
edge_kernel(const int* __restrict__ srcArr,
            const int* __restrict__ dstArr,
            const float2* __restrict__ wArr,
            const float* __restrict__ x,
            const float* __restrict__ A,
            const float* __restrict__ B,
            const float* __restrict__ Wm1,
            const float* __restrict__ Wm2,
            const float* __restrict__ bm2,
            const float* __restrict__ W2,
            const float* __restrict__ b2,
            float* __restrict__ out,
            int E) {
    constexpr int C4  = (C_IN + 3) / 4;
    constexpr int CIP = C4 * 4;
    constexpr int CO4 = (C_OUT + 3) / 4;
    constexpr int COP = CO4 * 4;

    __shared__ __align__(16) float sWE[2 * NMSG];
    __shared__ __align__(16) float sWm2[NMSG * CIP];
    __shared__ __align__(16) float sW2[C_IN * COP];
    __shared__ float sbm2[C_IN];
    __shared__ __align__(16) float sb2[COP];

    const int tid = threadIdx.x;
    for (int i = tid; i < 2 * NMSG; i += 256) sWE[i] = Wm1[2 * C_IN * NMSG + i];
    for (int i = tid; i < NMSG * CIP; i += 256) {
        int k = i / CIP, c = i - k * CIP;
        sWm2[i] = (c < C_IN) ? Wm2[k * C_IN + c] : 0.f;
    }
    for (int i = tid; i < C_IN * COP; i += 256) {
        int c = i / COP, co = i - c * COP;
        sW2[i] = (co < C_OUT) ? W2[c * C_OUT + co] : 0.f;
    }
    for (int i = tid; i < C_IN; i += 256) sbm2[i] = bm2[i];
    for (int i = tid; i < COP; i += 256) sb2[i] = (i < C_OUT) ? b2[i] : 0.f;
    __syncthreads();

    int e = blockIdx.x * 256 + tid;
    if (e >= E) return;

    const int src = srcArr[e];
    const int dst = dstArr[e];
    const float2 w = wArr[e];

    // xi - xj for all channels
    float dreg[C_IN];
#pragma unroll
    for (int c = 0; c < C_IN; c++) {
        float xi = x[(size_t)dst * C_IN + c];
        float xj = x[(size_t)src * C_IN + c];
        if (RELU_IN) { xi = fmaxf(xi, 0.f); xj = fmaxf(xj, 0.f); }
        dreg[c] = xi - xj;
    }

    const float4* A4  = (const float4*)(A + (size_t)dst * NMSG);
    const float4* B4  = (const float4*)(B + (size_t)src * NMSG);
    const float4* WE0 = (const float4*)(sWE);
    const float4* WE1 = (const float4*)(sWE + NMSG);

    float4 macc[C4];
#pragma unroll
    for (int j = 0; j < C4; j++) macc[j] = make_float4(0.f, 0.f, 0.f, 0.f);

#pragma unroll 2
    for (int kg = 0; kg < NMSG / 4; kg++) {
        float4 a = A4[kg];
        float4 b = B4[kg];
        float4 u0 = WE0[kg];
        float4 u1 = WE1[kg];
        float hx = fmaxf(fmaf(w.x, u0.x, fmaf(w.y, u1.x, a.x + b.x)), 0.f);
        float hy = fmaxf(fmaf(w.x, u0.y, fmaf(w.y, u1.y, a.y + b.y)), 0.f);
        float hz = fmaxf(fmaf(w.x, u0.z, fmaf(w.y, u1.z, a.z + b.z)), 0.f);
        float hw = fmaxf(fmaf(w.x, u0.w, fmaf(w.y, u1.w, a.w + b.w)), 0.f);

        const float4* r0 = (const float4*)(sWm2 + (4 * kg + 0) * CIP);
        const float4* r1 = (const float4*)(sWm2 + (4 * kg + 1) * CIP);
        const float4* r2 = (const float4*)(sWm2 + (4 * kg + 2) * CIP);
        const float4* r3 = (const float4*)(sWm2 + (4 * kg + 3) * CIP);
#pragma unroll
        for (int j = 0; j < C4; j++) {
            float4 q0 = r0[j], q1 = r1[j], q2 = r2[j], q3 = r3[j];
            macc[j].x = fmaf(hx, q0.x, fmaf(hy, q1.x, fmaf(hz, q2.x, fmaf(hw, q3.x, macc[j].x))));
            macc[j].y = fmaf(hx, q0.y, fmaf(hy, q1.y, fmaf(hz, q2.y, fmaf(hw, q3.y, macc[j].y))));
            macc[j].z = fmaf(hx, q0.z, fmaf(hy, q1.z, fmaf(hz, q2.z, fmaf(hw, q3.z, macc[j].z))));
            macc[j].w = fmaf(hx, q0.w, fmaf(hy, q1.w, fmaf(hz, q2.w, fmaf(hw, q3.w, macc[j].w))));
        }
    }

    // t_c = (m_c + bm2_c) * (xi - xj)_c
#pragma unroll
    for (int j = 0; j < C4; j++) {
        int c = 4 * j;
        if (c + 0 < C_IN) dreg[c + 0] = (macc[j].x + sbm2[c + 0]) * dreg[c + 0];
        if (c + 1 < C_IN) dreg[c + 1] = (macc[j].y + sbm2[c + 1]) * dreg[c + 1];
        if (c + 2 < C_IN) dreg[c + 2] = (macc[j].z + sbm2[c + 2]) * dreg[c + 2];
        if (c + 3 < C_IN) dreg[c + 3] = (macc[j].w + sbm2[c + 3]) * dreg[c + 3];
    }

    // msg = t @ W2 + b2
    float4 vacc[CO4];
    const float4* sb24 = (const float4*)sb2;
#pragma unroll
    for (int j = 0; j < CO4; j++) vacc[j] = sb24[j];
#pragma unroll
    for (int c = 0; c < C_IN; c++) {
        float tv = dreg[c];
        const float4* wr = (const float4*)(sW2 + c * COP);
#pragma unroll
        for (int j = 0; j < CO4; j++) {
            float4 q = wr[j];
            vacc[j].x = fmaf(tv, q.x, vacc[j].x);
            vacc[j].y = fmaf(tv, q.y, vacc[j].y);
            vacc[j].z = fmaf(tv, q.z, vacc[j].z);
            vacc[j].w = fmaf(tv, q.w, vacc[j].w);
        }
    }

    float* op = out + (size_t)dst * C_OUT;
#pragma unroll
    for (int j = 0; j < CO4; j++) {
        int co = 4 * j;
        if (co + 0 < C_OUT) atomicAdd(op + co + 0, vacc[j].x);
        if (co + 1 < C_OUT) atomicAdd(op + co + 1, vacc[j].y);
        if (co + 2 < C_OUT) atomicAdd(op + co + 2, vacc[j].z);
        if (co + 3 < C_OUT) atomicAdd(op + co + 3, vacc[j].w);
    }
}

// ---------------------------------------------------------------------------
// Host-side layer driver
// ---------------------------------------------------------------------------
template <int C_IN, int C_OUT, bool RELU_IN>
static void run_layer(const float* xin,
                      const float* const* W,   // W1,b1,Wm1,bm1,Wm2,bm2,W2,b2
                      const int* ssrc, const int* sdst, const float2* sw,
                      float* Abuf, float* Bbuf,
                      float* xout,
                      int N, int E) {
    precomp_ab_kernel<C_IN, RELU_IN><<<(N * NMSG + 255) / 256, 256>>>(
        xin, W[2], W[3], Abuf, Bbuf, N);
    node_init_kernel<C_IN, C_OUT, RELU_IN><<<(N * C_OUT + 255) / 256, 256>>>(
        xin, W[0], W[1], xout, N);
    edge_kernel<C_IN, C_OUT, RELU_IN><<<(E + 255) / 256, 256>>>(
        ssrc, sdst, sw, xin, Abuf, Bbuf, W[2], W[4], W[5], W[6], W[7], xout, E);
}

extern "C" void kernel_launch(void* const* d_in, const int* in_sizes, int n_in,
                              void* d_out, int out_size) {
    const float* feat  = (const float*)d_in[0];
    const void*  edges = d_in[1];
    const float* ew    = (const float*)d_in[2];

    const float* P[24];
    for (int i = 0; i < 24; i++) P[i] = (const float*)d_in[3 + i];
    // P[0..7] = layer d, P[8..15] = layer h, P[16..23] = layer o

    int N = in_sizes[0];        // NUM_IN == 1 -> element count == node count
    int E = in_sizes[2] / 2;    // weights is [E,2]

    float *x0, *x1, *A, *B;
    int *ssrc, *sdst;
    float2 *sw;
    cudaGetSymbolAddress((void**)&x0,   g_x0);
    cudaGetSymbolAddress((void**)&x1,   g_x1);
    cudaGetSymbolAddress((void**)&A,    g_A);
    cudaGetSymbolAddress((void**)&B,    g_B);
    cudaGetSymbolAddress((void**)&ssrc, g_ssrc);
    cudaGetSymbolAddress((void**)&sdst, g_sdst);
    cudaGetSymbolAddress((void**)&sw,   g_sw);

    // One-time (per launch) preprocessing: dtype detect + counting sort by dst
    detect_edges_kernel<<<1, 32>>>((const long long*)edges);
    zero_hist_kernel<<<(N + 255) / 256, 256>>>(N);
    hist_kernel<<<(E + 255) / 256, 256>>>(edges, E);
    scan_kernel<<<1, 1024>>>(N);
    scatter_kernel<<<(E + 255) / 256, 256>>>(edges, ew, E);

    run_layer<1, 30, false>(feat, P + 0,  ssrc, sdst, sw, A, B, x0, N, E);
    run_layer<30, 30, true>(x0,  P + 8,  ssrc, sdst, sw, A, B, x1, N, E);
    run_layer<30, 30, true>(x1,  P + 8,  ssrc, sdst, sw, A, B, x0, N, E);
    run_layer<30, 30, true>(x0,  P + 8,  ssrc, sdst, sw, A, B, x1, N, E);
    run_layer<30, 1, true>(x1,   P + 16, ssrc, sdst, sw, A, B, (float*)d_out, N, E);
}